// round 11
// baseline (speedup 1.0000x reference)
#include <cuda_runtime.h>
#include <cstdint>

#define S_LEN   4096
#define NTASKS  256
#define NALGOS  64
#define WARM    192
#define CHUNK   256
#define NCHUNK  16
#define NCHAINS (NALGOS * NCHUNK)
#define CHAIN_BLOCKS (NCHAINS / 4)

// prep[a][s] = {T1w_s, BC_{s+1}, AC_{s+2}, TM3_s} for the D=3 deferred chain
__device__ __align__(16) float4 prep_buf[NALGOS * S_LEN];
// handoff: per (a,chunk) k-values and res seed at the chunk seam
__device__ __align__(16) float k_glob[NCHAINS][CHUNK];
__device__ __align__(16) float seed_glob[NCHAINS][NTASKS];
__device__ int chain_done[NCHAINS];

__device__ __forceinline__ float rcpf(float x) {
    float y; asm("rcp.approx.f32 %0, %1;" : "=f"(y) : "f"(x)); return y;
}
__device__ __forceinline__ float tanhapx(float x) {
    float y; asm("tanh.approx.f32 %0, %1;" : "=f"(y) : "f"(x)); return y;
}
__device__ __forceinline__ float ldcgf(const float* p) {
    float v; asm volatile("ld.global.cg.f32 %0, [%1];" : "=f"(v) : "l"(p)); return v;
}

#define PACK64(u, lo, hi)   asm("mov.b64 %0, {%1, %2};" : "=l"(u) : "f"(lo), "f"(hi))
#define UNPACK64(lo, hi, u) asm("mov.b64 {%0, %1}, %2;" : "=f"(lo), "=f"(hi) : "l"(u))
#define MULX2(o, a, b)      asm("mul.rn.f32x2 %0, %1, %2;" : "=l"(o) : "l"(a), "l"(b))
#define FMAX2(o, a, b, c)   asm("fma.rn.f32x2 %0, %1, %2, %3;" : "=l"(o) : "l"(a), "l"(b), "l"(c))

// ---------------------------------------------------------------------------
// Prep: coefficient packing, flag reset, output col-0 zeroing.
// ---------------------------------------------------------------------------
__global__ void __launch_bounds__(128) idl_prep(
    const int* __restrict__ lx, const float* __restrict__ tm,
    const float* __restrict__ diff, const float* __restrict__ memA,
    float* __restrict__ out)
{
    if (blockIdx.x == 0) {
        for (int i = threadIdx.x; i < NCHAINS; i += 128)
            chain_done[i] = 0;
    }
    if (blockIdx.x < 128) {
        const int idx = blockIdx.x * 128 + threadIdx.x;   // (a*256+c)
        out[(size_t)idx * (size_t)(S_LEN + 1)] = 0.0f;
    }

    const int a = blockIdx.x >> 5;
    const int s = ((blockIdx.x & 31) << 7) + threadIdx.x;
    const float mem = memA[a];

    const int t0 = __ldg(lx + s);
    const int t1 = __ldg(lx + min(s + 1, S_LEN - 1));
    const int t2 = __ldg(lx + min(s + 2, S_LEN - 1));
    const int t3 = __ldg(lx + min(s + 3, S_LEN - 1));

    const float wh1 = 0.5f * rcpf(__ldg(diff + t1));
    const float wh2 = 0.5f * rcpf(__ldg(diff + t2));
    const float wh3 = 0.5f * rcpf(__ldg(diff + t3));

    float4 o;
    o.x = __ldg(tm + t0 * NTASKS + t1) * wh1;
    o.y = __ldg(tm + t0 * NTASKS + t2) * (wh2 * mem);
    o.z = wh3 * mem * mem;
    o.w = __ldg(tm + t0 * NTASKS + t3);
    prep_buf[a * S_LEN + s] = o;
}

// ---------------------------------------------------------------------------
// Fused work kernel.
// Blocks [0, 256): chain — one k-chain per warp (D=3 deferred, 8-deep ring),
//   releases chain_done[bq] when its chunk's k + seed are in global.
// Blocks [256, 2304): out — stages tm col-slice during chain execution, then
//   per-warp acquire-spins on its chunk flag and computes/stores the output.
// ---------------------------------------------------------------------------
__global__ void __launch_bounds__(128) idl_work(
    const int*   __restrict__ lx,
    const float* __restrict__ tm,
    const float* __restrict__ diff,
    const float* __restrict__ effA,
    const float* __restrict__ memA,
    const float* __restrict__ boostA,
    float*       __restrict__ out)
{
    __shared__ float    tm_sh[NTASKS * 32];        // 32 KB  [t][c_local]
    __shared__ float    kf_sh[4][CHUNK];           // 4 KB
    __shared__ uint16_t t16_sh[4][CHUNK];          // 2 KB   (t*32)
    __shared__ float    sbuf[4][32][33];           // 16.9 KB

    const int tid  = threadIdx.x;
    const int w    = tid >> 5;
    const int lane = tid & 31;

    if (blockIdx.x < CHAIN_BLOCKS) {
        // ===================== CHAIN =====================
        const int bq = blockIdx.x * 4 + w;         // global chain id
        const int a  = bq >> 4;
        const int q  = bq & 15;

        const float mem   = memA[a];
        const float eff   = effA[a];
        const float boost = boostA[a];

        const int warm_n = q ? WARM : 0;
        const int s0     = q * CHUNK;
        const int s_base = s0 - warm_n;

        uint64_t uu0 = 0, uu1 = 0, uu2 = 0, uu3 = 0;
        uint64_t memm; PACK64(memm, mem, mem);

        ulonglong2 rA[8], rB[8];
        #pragma unroll
        for (int i = 0; i < 8; i++) {
            const int t = __ldg(lx + min(s_base + i, S_LEN - 1));
            const ulonglong2* rp = (const ulonglong2*)(tm + t * NTASKS + lane * 8);
            rA[i] = rp[0];
            rB[i] = rp[1];
        }
        const float4* prp = prep_buf + a * S_LEN;
        float4 PF[8];
        #pragma unroll
        for (int i = 0; i < 8; i++)
            PF[i] = __ldg(prp + min(s_base + i, S_LEN - 1));

        float g = 0.0f, base = 0.0f, pb1 = 0.0f, Am = 0.0f;
        float kq[4];

        // warm region
        for (int ib = 0; ib < warm_n; ib += 16) {
            #pragma unroll
            for (int u = 0; u < 16; u++) {
                const int s = s_base + ib + u;
                const float4 pf = PF[u & 7];

                float k   = fmaf(boost, g, eff);
                float arg = fmaf(k, pf.x, base);
                g = tanhapx(arg);

                base = fmaf(k, pf.y, pb1);
                float inner = fmaf(k, pf.w, Am);
                pb1 = pf.z * inner;

                uint64_t kk; PACK64(kk, k, k);
                uint64_t p0, p1, p2, p3;
                MULX2(p0, rA[u & 7].x, kk); FMAX2(uu0, uu0, memm, p0);
                MULX2(p1, rA[u & 7].y, kk); FMAX2(uu1, uu1, memm, p1);
                MULX2(p2, rB[u & 7].x, kk); FMAX2(uu2, uu2, memm, p2);
                MULX2(p3, rB[u & 7].y, kk); FMAX2(uu3, uu3, memm, p3);

                const int cn = __ldg(lx + min(s + 4, S_LEN - 1));
                uint64_t sA = (cn & 2) ? uu1 : uu0;
                uint64_t sB = (cn & 2) ? uu3 : uu2;
                uint64_t sv = (cn & 4) ? sB : sA;
                float lo, hi; UNPACK64(lo, hi, sv);
                float v  = (cn & 1) ? hi : lo;
                float bc = __shfl_sync(0xffffffffu, v, cn >> 3);
                Am = mem * bc;

                const int t8 = __ldg(lx + min(s + 8, S_LEN - 1));
                const ulonglong2* rp = (const ulonglong2*)(tm + t8 * NTASKS + lane * 8);
                rA[u & 7] = rp[0];
                rB[u & 7] = rp[1];
                PF[u & 7] = __ldg(prp + min(s + 8, S_LEN - 1));
            }
        }

        // dump res seed (state after step s0-1)
        {
            ulonglong2* rs = (ulonglong2*)&seed_glob[bq][lane * 8];
            ulonglong2 d0; d0.x = uu0; d0.y = uu1;
            ulonglong2 d1; d1.x = uu2; d1.y = uu3;
            rs[0] = d0;
            rs[1] = d1;
        }

        // main region (emit k)
        float* kout = k_glob[bq];
        for (int ib = warm_n; ib < warm_n + CHUNK; ib += 16) {
            #pragma unroll
            for (int u = 0; u < 16; u++) {
                const int i = ib + u;
                const int s = s_base + i;
                const float4 pf = PF[u & 7];

                float k   = fmaf(boost, g, eff);
                float arg = fmaf(k, pf.x, base);
                g = tanhapx(arg);

                kq[u & 3] = k;
                if ((u & 3) == 3 && lane == 0)
                    *(float4*)(kout + (i - warm_n - 3)) =
                        make_float4(kq[0], kq[1], kq[2], kq[3]);

                base = fmaf(k, pf.y, pb1);
                float inner = fmaf(k, pf.w, Am);
                pb1 = pf.z * inner;

                uint64_t kk; PACK64(kk, k, k);
                uint64_t p0, p1, p2, p3;
                MULX2(p0, rA[u & 7].x, kk); FMAX2(uu0, uu0, memm, p0);
                MULX2(p1, rA[u & 7].y, kk); FMAX2(uu1, uu1, memm, p1);
                MULX2(p2, rB[u & 7].x, kk); FMAX2(uu2, uu2, memm, p2);
                MULX2(p3, rB[u & 7].y, kk); FMAX2(uu3, uu3, memm, p3);

                const int cn = __ldg(lx + min(s + 4, S_LEN - 1));
                uint64_t sA = (cn & 2) ? uu1 : uu0;
                uint64_t sB = (cn & 2) ? uu3 : uu2;
                uint64_t sv = (cn & 4) ? sB : sA;
                float lo, hi; UNPACK64(lo, hi, sv);
                float v  = (cn & 1) ? hi : lo;
                float bc = __shfl_sync(0xffffffffu, v, cn >> 3);
                Am = mem * bc;

                const int t8 = __ldg(lx + min(s + 8, S_LEN - 1));
                const ulonglong2* rp = (const ulonglong2*)(tm + t8 * NTASKS + lane * 8);
                rA[u & 7] = rp[0];
                rB[u & 7] = rp[1];
                PF[u & 7] = __ldg(prp + min(s + 8, S_LEN - 1));
            }
        }

        // publish: fence all lanes' writes, then release the flag
        __threadfence();
        __syncwarp();
        if (lane == 0)
            asm volatile("st.global.release.gpu.s32 [%0], %1;"
                         :: "l"(chain_done + bq), "r"(1) : "memory");
        return;
    }

    // ===================== OUT =====================
    const int b   = blockIdx.x - CHAIN_BLOCKS;
    const int a   = b >> 5;
    const int rem = b & 31;
    const int cg  = rem >> 2;           // colgroup 0..7 (32 cols)
    const int cq  = rem & 3;            // chunkgroup 0..3

    // stage tm column slice (overlaps chain execution)
    #pragma unroll
    for (int i = tid; i < NTASKS * 32; i += 128)
        tm_sh[i] = __ldg(tm + (i >> 5) * NTASKS + cg * 32 + (i & 31));
    __syncthreads();

    const int q  = cq * 4 + w;          // this warp's chunk
    const int s0 = q * CHUNK;
    const int bq = a * NCHUNK + q;

    // wait for this chunk's chain
    if (lane == 0) {
        int f;
        for (;;) {
            asm volatile("ld.global.acquire.gpu.s32 %0, [%1];"
                         : "=r"(f) : "l"(chain_done + bq) : "memory");
            if (f) break;
            __nanosleep(100);
        }
    }
    __syncwarp();

    // stage (t, k) stream (k via L2-coherent loads)
    for (int i = lane; i < CHUNK; i += 32) {
        kf_sh[w][i]  = ldcgf(&k_glob[bq][i]);
        t16_sh[w][i] = (uint16_t)(__ldg(lx + s0 + i) << 5);
    }
    __syncwarp();

    const int   col = cg * 32 + lane;
    const float mem = memA[a];
    const float wh  = 0.5f * rcpf(__ldg(diff + col));

    float r = ldcgf(&seed_glob[bq][col]);   // seeded: no warm-up

    float* outw = out + (size_t)(a * NTASKS + cg * 32) * (size_t)(S_LEN + 1)
                + 1 + s0 + lane;

    #pragma unroll 1
    for (int tile = 0; tile < CHUNK / 32; tile++) {
        #pragma unroll
        for (int j = 0; j < 32; j++) {
            const int idx = tile * 32 + j;
            const float tv = tm_sh[(int)t16_sh[w][idx] + lane];
            r = fmaf(r, mem, tv * kf_sh[w][idx]);
            sbuf[w][lane][j] = tanhapx(r * wh);
        }
        __syncwarp();
        const float* sb = &sbuf[w][0][lane];
        float* op = outw + tile * 32;
        #pragma unroll
        for (int cl = 0; cl < 32; cl++) {
            __stcs(op, *sb);
            op += (S_LEN + 1);
            sb += 33;
        }
        __syncwarp();
    }
}

extern "C" void kernel_launch(void* const* d_in, const int* in_sizes, int n_in,
                              void* d_out, int out_size)
{
    (void)in_sizes; (void)n_in; (void)out_size;
    const int*   lx    = (const int*)  d_in[0];
    const float* tm    = (const float*)d_in[1];
    const float* diff  = (const float*)d_in[2];
    const float* eff   = (const float*)d_in[3];
    const float* mem   = (const float*)d_in[4];
    const float* boost = (const float*)d_in[5];
    float*       out   = (float*)d_out;

    idl_prep<<<NALGOS * 32, 128>>>(lx, tm, diff, mem, out);
    idl_work<<<CHAIN_BLOCKS + NALGOS * 32, 128>>>(lx, tm, diff, eff, mem, boost, out);
}

// round 12
// speedup vs baseline: 1.1204x; 1.1204x over previous
#include <cuda_runtime.h>
#include <cstdint>

#define S_LEN   4096
#define NTASKS  256
#define NALGOS  64
#define WARM    192
#define CHUNK   256
#define NCHUNK  16
#define NCHAINS (NALGOS * NCHUNK)

// prep[a][s] = {T1w_s, BC_{s+1}, AC_{s+2}, TM3_s} for the D=3 deferred chain
__device__ __align__(16) float4 prep_buf[NALGOS * S_LEN];
// handoff: per (a,chunk) k-values and res seed at the chunk seam
__device__ __align__(16) float k_glob[NCHAINS][CHUNK];
__device__ __align__(16) float seed_glob[NCHAINS][NTASKS];
__device__ int chain_done[NCHAINS];

__device__ __forceinline__ float rcpf(float x) {
    float y; asm("rcp.approx.f32 %0, %1;" : "=f"(y) : "f"(x)); return y;
}
__device__ __forceinline__ float tanhapx(float x) {
    float y; asm("tanh.approx.f32 %0, %1;" : "=f"(y) : "f"(x)); return y;
}
__device__ __forceinline__ float ldcgf(const float* p) {
    float v; asm volatile("ld.global.cg.f32 %0, [%1];" : "=f"(v) : "l"(p)); return v;
}

#define PACK64(u, lo, hi)   asm("mov.b64 %0, {%1, %2};" : "=l"(u) : "f"(lo), "f"(hi))
#define UNPACK64(lo, hi, u) asm("mov.b64 {%0, %1}, %2;" : "=f"(lo), "=f"(hi) : "l"(u))
#define MULX2(o, a, b)      asm("mul.rn.f32x2 %0, %1, %2;" : "=l"(o) : "l"(a), "l"(b))
#define FMAX2(o, a, b, c)   asm("fma.rn.f32x2 %0, %1, %2, %3;" : "=l"(o) : "l"(a), "l"(b), "l"(c))

// ---------------------------------------------------------------------------
// Prep: coefficient packing, flag reset, output col-0 zeroing.
// ---------------------------------------------------------------------------
__global__ void __launch_bounds__(128) idl_prep(
    const int* __restrict__ lx, const float* __restrict__ tm,
    const float* __restrict__ diff, const float* __restrict__ memA,
    float* __restrict__ out)
{
    if (blockIdx.x == 0) {
        for (int i = threadIdx.x; i < NCHAINS; i += 128)
            chain_done[i] = 0;
    }
    if (blockIdx.x < 128) {
        const int idx = blockIdx.x * 128 + threadIdx.x;   // (a*256+c)
        out[(size_t)idx * (size_t)(S_LEN + 1)] = 0.0f;
    }

    const int a = blockIdx.x >> 5;
    const int s = ((blockIdx.x & 31) << 7) + threadIdx.x;
    const float mem = memA[a];

    const int t0 = __ldg(lx + s);
    const int t1 = __ldg(lx + min(s + 1, S_LEN - 1));
    const int t2 = __ldg(lx + min(s + 2, S_LEN - 1));
    const int t3 = __ldg(lx + min(s + 3, S_LEN - 1));

    const float wh1 = 0.5f * rcpf(__ldg(diff + t1));
    const float wh2 = 0.5f * rcpf(__ldg(diff + t2));
    const float wh3 = 0.5f * rcpf(__ldg(diff + t3));

    float4 o;
    o.x = __ldg(tm + t0 * NTASKS + t1) * wh1;
    o.y = __ldg(tm + t0 * NTASKS + t2) * (wh2 * mem);
    o.z = wh3 * mem * mem;
    o.w = __ldg(tm + t0 * NTASKS + t3);
    prep_buf[a * S_LEN + s] = o;
}

// ---------------------------------------------------------------------------
// Chain: 256 blocks x 128 threads, one chain per warp, NO smem.
// Triggers PDL at entry so idl_out can launch concurrently; publishes each
// chunk's k + seed via release flag.
// ---------------------------------------------------------------------------
__global__ void __launch_bounds__(128) idl_chain(
    const int*   __restrict__ lx,
    const float* __restrict__ tm,
    const float* __restrict__ effA,
    const float* __restrict__ memA,
    const float* __restrict__ boostA)
{
    // Let the dependent idl_out launch start now (it synchronizes via flags).
    cudaTriggerProgrammaticLaunchCompletion();

    const int w    = threadIdx.x >> 5;
    const int lane = threadIdx.x & 31;
    const int bq   = blockIdx.x * 4 + w;          // global chain id 0..1023
    const int a    = bq >> 4;
    const int q    = bq & 15;

    const float mem   = memA[a];
    const float eff   = effA[a];
    const float boost = boostA[a];

    const int warm_n = q ? WARM : 0;
    const int s0     = q * CHUNK;
    const int s_base = s0 - warm_n;

    uint64_t uu0 = 0, uu1 = 0, uu2 = 0, uu3 = 0;   // res cols lane*8+0..7
    uint64_t memm; PACK64(memm, mem, mem);

    ulonglong2 rA[8], rB[8];                       // 8-deep row ring
    #pragma unroll
    for (int i = 0; i < 8; i++) {
        const int t = __ldg(lx + min(s_base + i, S_LEN - 1));
        const ulonglong2* rp = (const ulonglong2*)(tm + t * NTASKS + lane * 8);
        rA[i] = rp[0];
        rB[i] = rp[1];
    }
    const float4* prp = prep_buf + a * S_LEN;
    float4 PF[8];
    #pragma unroll
    for (int i = 0; i < 8; i++)
        PF[i] = __ldg(prp + min(s_base + i, S_LEN - 1));

    float g = 0.0f, base = 0.0f, pb1 = 0.0f, Am = 0.0f;
    float kq[4];

    // ---- warm region ----
    for (int ib = 0; ib < warm_n; ib += 16) {
        #pragma unroll
        for (int u = 0; u < 16; u++) {
            const int s = s_base + ib + u;
            const float4 pf = PF[u & 7];

            float k   = fmaf(boost, g, eff);
            float arg = fmaf(k, pf.x, base);
            g = tanhapx(arg);

            base = fmaf(k, pf.y, pb1);
            float inner = fmaf(k, pf.w, Am);
            pb1 = pf.z * inner;

            uint64_t kk; PACK64(kk, k, k);
            uint64_t p0, p1, p2, p3;
            MULX2(p0, rA[u & 7].x, kk); FMAX2(uu0, uu0, memm, p0);
            MULX2(p1, rA[u & 7].y, kk); FMAX2(uu1, uu1, memm, p1);
            MULX2(p2, rB[u & 7].x, kk); FMAX2(uu2, uu2, memm, p2);
            MULX2(p3, rB[u & 7].y, kk); FMAX2(uu3, uu3, memm, p3);

            const int cn = __ldg(lx + min(s + 4, S_LEN - 1));
            uint64_t sA = (cn & 2) ? uu1 : uu0;
            uint64_t sB = (cn & 2) ? uu3 : uu2;
            uint64_t sv = (cn & 4) ? sB : sA;
            float lo, hi; UNPACK64(lo, hi, sv);
            float v  = (cn & 1) ? hi : lo;
            float bc = __shfl_sync(0xffffffffu, v, cn >> 3);
            Am = mem * bc;

            const int t8 = __ldg(lx + min(s + 8, S_LEN - 1));
            const ulonglong2* rp = (const ulonglong2*)(tm + t8 * NTASKS + lane * 8);
            rA[u & 7] = rp[0];
            rB[u & 7] = rp[1];
            PF[u & 7] = __ldg(prp + min(s + 8, S_LEN - 1));
        }
    }

    // ---- dump res seed (state after step s0-1) ----
    {
        ulonglong2* rs = (ulonglong2*)&seed_glob[bq][lane * 8];
        ulonglong2 d0; d0.x = uu0; d0.y = uu1;
        ulonglong2 d1; d1.x = uu2; d1.y = uu3;
        rs[0] = d0;
        rs[1] = d1;
    }

    // ---- main region (emit k) ----
    float* kout = k_glob[bq];
    for (int ib = warm_n; ib < warm_n + CHUNK; ib += 16) {
        #pragma unroll
        for (int u = 0; u < 16; u++) {
            const int i = ib + u;
            const int s = s_base + i;
            const float4 pf = PF[u & 7];

            float k   = fmaf(boost, g, eff);
            float arg = fmaf(k, pf.x, base);
            g = tanhapx(arg);

            kq[u & 3] = k;
            if ((u & 3) == 3 && lane == 0)
                *(float4*)(kout + (i - warm_n - 3)) =
                    make_float4(kq[0], kq[1], kq[2], kq[3]);

            base = fmaf(k, pf.y, pb1);
            float inner = fmaf(k, pf.w, Am);
            pb1 = pf.z * inner;

            uint64_t kk; PACK64(kk, k, k);
            uint64_t p0, p1, p2, p3;
            MULX2(p0, rA[u & 7].x, kk); FMAX2(uu0, uu0, memm, p0);
            MULX2(p1, rA[u & 7].y, kk); FMAX2(uu1, uu1, memm, p1);
            MULX2(p2, rB[u & 7].x, kk); FMAX2(uu2, uu2, memm, p2);
            MULX2(p3, rB[u & 7].y, kk); FMAX2(uu3, uu3, memm, p3);

            const int cn = __ldg(lx + min(s + 4, S_LEN - 1));
            uint64_t sA = (cn & 2) ? uu1 : uu0;
            uint64_t sB = (cn & 2) ? uu3 : uu2;
            uint64_t sv = (cn & 4) ? sB : sA;
            float lo, hi; UNPACK64(lo, hi, sv);
            float v  = (cn & 1) ? hi : lo;
            float bc = __shfl_sync(0xffffffffu, v, cn >> 3);
            Am = mem * bc;

            const int t8 = __ldg(lx + min(s + 8, S_LEN - 1));
            const ulonglong2* rp = (const ulonglong2*)(tm + t8 * NTASKS + lane * 8);
            rA[u & 7] = rp[0];
            rB[u & 7] = rp[1];
            PF[u & 7] = __ldg(prp + min(s + 8, S_LEN - 1));
        }
    }

    // publish: fence all lanes' writes, then release the flag
    __threadfence();
    __syncwarp();
    if (lane == 0)
        asm volatile("st.global.release.gpu.s32 [%0], %1;"
                     :: "l"(chain_done + bq), "r"(1) : "memory");
}

// ---------------------------------------------------------------------------
// Out: 2048 blocks = 64 algos x 8 colgroups x 4 chunkgroups, 128 threads.
// Launched with PDL so it overlaps idl_chain; stages tm slice immediately,
// then per-warp acquire-spins on its chunk's flag.
// ---------------------------------------------------------------------------
__global__ void __launch_bounds__(128) idl_out(
    const int*   __restrict__ lx,
    const float* __restrict__ tm,
    const float* __restrict__ diff,
    const float* __restrict__ memA,
    float*       __restrict__ out)
{
    __shared__ float    tm_sh[NTASKS * 32];        // 32 KB: [t][c_local]
    __shared__ float    kf_sh[4][CHUNK];           // 4 KB
    __shared__ uint16_t t16_sh[4][CHUNK];          // 2 KB  (t*32)
    __shared__ float    sbuf[4][32][33];           // 16.9 KB

    const int b    = blockIdx.x;
    const int a    = b >> 5;
    const int rem  = b & 31;
    const int cg   = rem >> 2;          // colgroup 0..7 (32 cols each)
    const int cq   = rem & 3;           // chunkgroup 0..3
    const int tid  = threadIdx.x;
    const int w    = tid >> 5;
    const int lane = tid & 31;

    // stage tm column slice (input-only; safe before chain completes)
    #pragma unroll
    for (int i = tid; i < NTASKS * 32; i += 128)
        tm_sh[i] = __ldg(tm + (i >> 5) * NTASKS + cg * 32 + (i & 31));
    __syncthreads();

    const int q  = cq * 4 + w;          // this warp's chunk
    const int s0 = q * CHUNK;
    const int bq = a * NCHUNK + q;

    // wait for this chunk's chain
    if (lane == 0) {
        int f;
        for (;;) {
            asm volatile("ld.global.acquire.gpu.s32 %0, [%1];"
                         : "=r"(f) : "l"(chain_done + bq) : "memory");
            if (f) break;
            __nanosleep(100);
        }
    }
    __syncwarp();

    // stage (t, k) stream (k/seed via L2-coherent loads)
    for (int i = lane; i < CHUNK; i += 32) {
        kf_sh[w][i]  = ldcgf(&k_glob[bq][i]);
        t16_sh[w][i] = (uint16_t)(__ldg(lx + s0 + i) << 5);
    }
    __syncwarp();

    const int   col = cg * 32 + lane;
    const float mem = memA[a];
    const float wh  = 0.5f * rcpf(__ldg(diff + col));

    float r = ldcgf(&seed_glob[bq][col]);   // seeded: no warm-up

    float* outw = out + (size_t)(a * NTASKS + cg * 32) * (size_t)(S_LEN + 1)
                + 1 + s0 + lane;

    #pragma unroll 1
    for (int tile = 0; tile < CHUNK / 32; tile++) {
        #pragma unroll
        for (int j = 0; j < 32; j++) {
            const int idx = tile * 32 + j;
            const float tv = tm_sh[(int)t16_sh[w][idx] + lane];
            r = fmaf(r, mem, tv * kf_sh[w][idx]);
            sbuf[w][lane][j] = tanhapx(r * wh);
        }
        __syncwarp();
        // store: 32 column-runs of 32 floats (128B contiguous per STG-warp)
        const float* sb = &sbuf[w][0][lane];
        float* op = outw + tile * 32;
        #pragma unroll
        for (int cl = 0; cl < 32; cl++) {
            __stcs(op, *sb);
            op += (S_LEN + 1);
            sb += 33;
        }
        __syncwarp();
    }
}

extern "C" void kernel_launch(void* const* d_in, const int* in_sizes, int n_in,
                              void* d_out, int out_size)
{
    (void)in_sizes; (void)n_in; (void)out_size;
    const int*   lx    = (const int*)  d_in[0];
    const float* tm    = (const float*)d_in[1];
    const float* diff  = (const float*)d_in[2];
    const float* eff   = (const float*)d_in[3];
    const float* mem   = (const float*)d_in[4];
    const float* boost = (const float*)d_in[5];
    float*       out   = (float*)d_out;

    idl_prep<<<NALGOS * 32, 128>>>(lx, tm, diff, mem, out);
    idl_chain<<<NCHAINS / 4, 128>>>(lx, tm, eff, mem, boost);

    // idl_out launched with programmatic dependent launch: may start while
    // idl_chain is running (correctness via chain_done acquire/release).
    {
        cudaLaunchConfig_t cfg = {};
        cfg.gridDim  = dim3(NALGOS * 32, 1, 1);
        cfg.blockDim = dim3(128, 1, 1);
        cfg.dynamicSmemBytes = 0;
        cfg.stream = 0;
        cudaLaunchAttribute attr[1];
        attr[0].id = cudaLaunchAttributeProgrammaticStreamSerialization;
        attr[0].val.programmaticStreamSerializationAllowed = 1;
        cfg.attrs = attr;
        cfg.numAttrs = 1;
        cudaLaunchKernelEx(&cfg, idl_out, lx, tm, diff, mem, out);
    }
}